// round 3
// baseline (speedup 1.0000x reference)
#include <cuda_runtime.h>
#include <cuda_bf16.h>
#include <stdint.h>
#include <math.h>

// ---------------- problem dims ----------------
#define BATCH 256
#define TSTEPS 250
#define INDIM 700
#define HDIM 256
#define ODIM 20
#define KBR 4
#define BT (BATCH * TSTEPS)   // 64000
#define INPAD 704
#define HK 1024               // H*K
#define NR 128                // padded readout rows
#define KE1 (2 * INPAD)       // hi/lo folded K: 1408
#define KE2 (2 * HDIM)        // 512

// ---------------- scratch ----------------
__device__ __align__(16) __nv_bfloat16 g_Xbf[(size_t)BT * INPAD];
__device__ __align__(16) __nv_bfloat16 g_W1s[(size_t)HK * KE1];
__device__ __align__(16) __nv_bfloat16 g_W2s[(size_t)HK * KE2];
__device__ __align__(16) __nv_bfloat16 g_Wrs[(size_t)NR * KE2];
__device__ __align__(16) float         g_C[(size_t)BT * HK];
__device__ __align__(16) __nv_bfloat16 g_S1[(size_t)BT * HDIM];
__device__ __align__(16) __nv_bfloat16 g_S2[(size_t)BT * HDIM];

// ---------------- prep kernels ----------------
__global__ void prep_x_kernel(const float* __restrict__ x) {
    size_t i = (size_t)blockIdx.x * blockDim.x + threadIdx.x;
    if (i >= (size_t)BT * INPAD) return;
    int r = (int)(i / INPAD);
    int c = (int)(i % INPAD);
    float v = (c < INDIM) ? x[(size_t)r * INDIM + c] : 0.f;
    g_Xbf[i] = __float2bfloat16(v);
}

// hi/lo residual split: W = hi + lo (+ O(2^-17))
__global__ void prep_w_kernel(const float* __restrict__ W, int Nin, int Npad,
                              int Kin, int Kpad, int which) {
    __nv_bfloat16* dst = (which == 0) ? g_W1s : (which == 1) ? g_W2s : g_Wrs;
    size_t total = (size_t)Npad * Kpad;
    size_t i = (size_t)blockIdx.x * blockDim.x + threadIdx.x;
    if (i >= total) return;
    int n = (int)(i / Kpad);
    int c = (int)(i % Kpad);
    float v = (n < Nin && c < Kin) ? W[(size_t)n * Kin + c] : 0.f;
    __nv_bfloat16 hi = __float2bfloat16(v);
    float lo = v - __bfloat162float(hi);
    dst[(size_t)n * (2 * Kpad) + c] = hi;
    dst[(size_t)n * (2 * Kpad) + Kpad + c] = __float2bfloat16(lo);
}

// ---------------- asm helpers ----------------
__device__ __forceinline__ uint32_t smem_u32(const void* p) {
    uint32_t a;
    asm("{ .reg .u64 t; cvta.to.shared.u64 t, %1; cvt.u32.u64 %0, t; }" : "=r"(a) : "l"(p));
    return a;
}
__device__ __forceinline__ void cp16s(uint32_t d, const void* s) {
    asm volatile("cp.async.cg.shared.global [%0], [%1], 16;\n" :: "r"(d), "l"(s));
}
#define CP_COMMIT() asm volatile("cp.async.commit_group;\n")
#define CP_WAIT(n)  asm volatile("cp.async.wait_group %0;\n" :: "n"(n))

__device__ __forceinline__ void ldsm4(uint32_t (&r)[4], uint32_t addr) {
    asm volatile("ldmatrix.sync.aligned.m8n8.x4.shared.b16 {%0,%1,%2,%3}, [%4];"
                 : "=r"(r[0]), "=r"(r[1]), "=r"(r[2]), "=r"(r[3]) : "r"(addr));
}
__device__ __forceinline__ void mma16816(float (&d)[4], const uint32_t (&a)[4],
                                         const uint32_t b0, const uint32_t b1) {
    asm volatile(
        "mma.sync.aligned.m16n8k16.row.col.f32.bf16.bf16.f32 "
        "{%0,%1,%2,%3}, {%4,%5,%6,%7}, {%8,%9}, {%0,%1,%2,%3};\n"
        : "+f"(d[0]), "+f"(d[1]), "+f"(d[2]), "+f"(d[3])
        : "r"(a[0]), "r"(a[1]), "r"(a[2]), "r"(a[3]), "r"(b0), "r"(b1));
}

// ---------------- mma.sync GEMM: C[M,N] = A[M,K'] @ B[N,K']^T ----------------
// CTA tile 128 x BN, K-slab 32, 4-stage cp.async, ldmatrix fragments.
// A column index folds mod FOLDK (hi/lo weight trick: [X|X] vs [Whi|Wlo]).
#define ROWB 80   // padded row pitch in bytes (40 halfs): conflict-free ldmatrix

template <int BN, int KEXT, int FOLDK>
__device__ __forceinline__ void gemm_body(const __nv_bfloat16* __restrict__ A, int lda,
                                          const __nv_bfloat16* __restrict__ B, int ldb,
                                          float* __restrict__ C, int ldc) {
    constexpr int NSLAB = KEXT / 32;
    constexpr int ASTB = 128 * ROWB;   // A stage bytes
    constexpr int BSTB = BN * ROWB;
    constexpr int NT = BN / 32;        // n8 tiles per warp (8 for BN=256, 4 for 128)

    extern __shared__ __align__(16) char smem[];
    const uint32_t sbA = smem_u32(smem);
    const uint32_t sbB = sbA + 4 * ASTB;

    const int tid = threadIdx.x;
    const int lane = tid & 31, warp = tid >> 5;
    const int wm = warp & 1;          // 2 warps along M (64 rows each)
    const int wn = warp >> 1;         // 4 warps along N (BN/4 cols each)
    const int m0 = blockIdx.y * 128;
    const int n0 = blockIdx.x * BN;

    float acc[4][NT][4];
#pragma unroll
    for (int i = 0; i < 4; ++i)
#pragma unroll
        for (int j = 0; j < NT; ++j)
#pragma unroll
            for (int q = 0; q < 4; ++q) acc[i][j][q] = 0.f;

    // fill thread mapping: chunk c -> row c/4, 16B-group c%4
    const int fr = tid >> 2, fg = (tid & 3) * 16;  // row, byte offset (8 halfs)

    auto fill = [&](int s) {
        const int st = s & 3;
        const int kb = s * 32;
        const int ka = (kb >= FOLDK) ? kb - FOLDK : kb;
        const __nv_bfloat16* Ab = A + (size_t)(m0 + fr) * lda + ka + (fg >> 1);
        const __nv_bfloat16* Bb = B + (size_t)(n0 + fr) * ldb + kb + (fg >> 1);
        uint32_t dA = sbA + st * ASTB + fr * ROWB + fg;
        uint32_t dB = sbB + st * BSTB + fr * ROWB + fg;
#pragma unroll
        for (int i = 0; i < 2; ++i)  // 128 rows x 4 chunks / 256 thr
            cp16s(dA + i * 64 * ROWB, Ab + (size_t)i * 64 * lda);
#pragma unroll
        for (int i = 0; i < BN / 64; ++i)
            cp16s(dB + i * 64 * ROWB, Bb + (size_t)i * 64 * ldb);
        CP_COMMIT();
    };

    fill(0); fill(1); fill(2);

    // ldmatrix lane addressing (byte offsets within a stage)
    const uint32_t aOff = (uint32_t)(wm * 64 + (lane & 15)) * ROWB + ((lane >> 4) << 4);
    const uint32_t bOff = (uint32_t)(wn * (BN / 4) + (lane & 7) + ((lane >> 4) & 1) * 8) * ROWB
                        + (((lane >> 3) & 1) << 4);

    for (int s = 0; s < NSLAB; ++s) {
        if (s + 3 < NSLAB) { fill(s + 3); CP_WAIT(3); }
        else if (s + 2 < NSLAB) CP_WAIT(2);
        else if (s + 1 < NSLAB) CP_WAIT(1);
        else CP_WAIT(0);
        __syncthreads();

        const uint32_t sA = sbA + (s & 3) * ASTB;
        const uint32_t sB = sbB + (s & 3) * BSTB;
#pragma unroll
        for (int kk = 0; kk < 2; ++kk) {   // two k16 halves of the 32-slab
            uint32_t a[4][4];
#pragma unroll
            for (int mt = 0; mt < 4; ++mt)
                ldsm4(a[mt], sA + aOff + (uint32_t)mt * 16 * ROWB + kk * 32);
            uint32_t b[NT / 2][4];
#pragma unroll
            for (int np = 0; np < NT / 2; ++np)
                ldsm4(b[np], sB + bOff + (uint32_t)np * 16 * ROWB + kk * 32);
#pragma unroll
            for (int mt = 0; mt < 4; ++mt)
#pragma unroll
                for (int nt = 0; nt < NT; ++nt)
                    mma16816(acc[mt][nt], a[mt], b[nt >> 1][(nt & 1) * 2],
                             b[nt >> 1][(nt & 1) * 2 + 1]);
        }
        __syncthreads();
    }

    // epilogue: direct fp32 stores (32B contiguous per 4 lanes)
#pragma unroll
    for (int mt = 0; mt < 4; ++mt) {
        const int row = m0 + wm * 64 + mt * 16 + (lane >> 2);
        float* Cr0 = C + (size_t)row * ldc + n0 + wn * (BN / 4) + (lane & 3) * 2;
        float* Cr1 = Cr0 + (size_t)8 * ldc;
#pragma unroll
        for (int nt = 0; nt < NT; ++nt) {
            *(float2*)(Cr0 + nt * 8) = make_float2(acc[mt][nt][0], acc[mt][nt][1]);
            *(float2*)(Cr1 + nt * 8) = make_float2(acc[mt][nt][2], acc[mt][nt][3]);
        }
    }
}

__global__ __launch_bounds__(256, 1) void gemm1_k() {
    gemm_body<256, KE1, INPAD>(g_Xbf, INPAD, g_W1s, KE1, g_C, HK);
}
__global__ __launch_bounds__(256, 1) void gemm2_k() {
    gemm_body<256, KE2, HDIM>(g_S1, HDIM, g_W2s, KE2, g_C, HK);
}
__global__ __launch_bounds__(256, 1) void gemm3_k() {
    gemm_body<128, KE2, HDIM>(g_S2, HDIM, g_Wrs, KE2, g_C, NR);
}

// ---------------- time scans ----------------
__global__ void scan_layer_kernel(const float* __restrict__ bias,
                                  const float* __restrict__ tau_n,
                                  const float* __restrict__ tau_m,
                                  int which) {
    const int h = threadIdx.x;
    const int b = blockIdx.x;
    __nv_bfloat16* S = which ? g_S2 : g_S1;

    float be[KBR], ob[KBR], bi[KBR];
#pragma unroll
    for (int k = 0; k < KBR; ++k) {
        float s = 1.f / (1.f + expf(-tau_n[h * KBR + k]));
        be[k] = s;
        ob[k] = 1.f - s;
        bi[k] = bias[h * KBR + k];
    }
    float al = 1.f / (1.f + expf(-tau_m[h]));
    float oa = 1.f - al;

    float d0 = 0.f, d1 = 0.f, d2 = 0.f, d3 = 0.f, m = 0.f, sp = 0.f;
    const float4* Cf = (const float4*)g_C;
    size_t base = (size_t)b * TSTEPS * (HK / 4) + h;

#pragma unroll 2
    for (int t = 0; t < TSTEPS; ++t) {
        float4 c = Cf[base + (size_t)t * (HK / 4)];
        d0 = be[0] * d0 + ob[0] * (c.x + bi[0]);
        d1 = be[1] * d1 + ob[1] * (c.y + bi[1]);
        d2 = be[2] * d2 + ob[2] * (c.z + bi[2]);
        d3 = be[3] * d3 + ob[3] * (c.w + bi[3]);
        m = al * m + oa * (d0 + d1 + d2 + d3) - sp;
        sp = (m > 1.0f) ? 1.0f : 0.0f;
        S[((size_t)b * TSTEPS + t) * HDIM + h] = __float2bfloat16(sp);
    }
}

__global__ void scan_readout_kernel(const float* __restrict__ br,
                                    const float* __restrict__ tau_mr,
                                    const void* __restrict__ warm,
                                    float* __restrict__ out) {
    const int o = threadIdx.x;
    const int b = blockIdx.x;
    if (o >= ODIM) return;
    int w = *(const int*)warm;
    if (w < 0 || w > TSTEPS) w = (int)(*(const float*)warm);
    float al = 1.f / (1.f + expf(-tau_mr[o]));
    float oa = 1.f - al;
    float bo = br[o];
    float mr = 0.f, acc = 0.f;
    size_t base = (size_t)b * TSTEPS * NR + o;
#pragma unroll 5
    for (int t = 0; t < TSTEPS; ++t) {
        float v = g_C[base + (size_t)t * NR];
        mr = al * mr + oa * (v + bo);
        if (t >= w) acc += mr;
    }
    out[b * ODIM + o] = acc / (float)(TSTEPS - w);
}

// ---------------- launch ----------------
extern "C" void kernel_launch(void* const* d_in, const int* in_sizes, int n_in,
                              void* d_out, int out_size) {
    const float* x      = (const float*)d_in[0];
    const float* W1     = (const float*)d_in[1];
    const float* b1     = (const float*)d_in[2];
    const float* tau_n1 = (const float*)d_in[3];
    const float* tau_m1 = (const float*)d_in[4];
    const float* W2     = (const float*)d_in[5];
    const float* b2     = (const float*)d_in[6];
    const float* tau_n2 = (const float*)d_in[7];
    const float* tau_m2 = (const float*)d_in[8];
    const float* Wr     = (const float*)d_in[9];
    const float* br     = (const float*)d_in[10];
    const float* tau_mr = (const float*)d_in[11];
    const void*  warm   = d_in[12];
    float* out = (float*)d_out;

    const int smem12 = 4 * (128 * ROWB + 256 * ROWB);  // 122880
    const int smem3  = 4 * (128 * ROWB + 128 * ROWB);  // 81920
    cudaFuncSetAttribute(gemm1_k, cudaFuncAttributeMaxDynamicSharedMemorySize, smem12);
    cudaFuncSetAttribute(gemm2_k, cudaFuncAttributeMaxDynamicSharedMemorySize, smem12);
    cudaFuncSetAttribute(gemm3_k, cudaFuncAttributeMaxDynamicSharedMemorySize, smem3);

    prep_x_kernel<<<(int)(((size_t)BT * INPAD + 255) / 256), 256>>>(x);
    prep_w_kernel<<<(HK * INPAD + 255) / 256, 256>>>(W1, HK, HK, INDIM, INPAD, 0);
    prep_w_kernel<<<(HK * HDIM + 255) / 256, 256>>>(W2, HK, HK, HDIM, HDIM, 1);
    prep_w_kernel<<<(NR * HDIM + 255) / 256, 256>>>(Wr, ODIM, NR, HDIM, HDIM, 2);

    gemm1_k<<<dim3(4, 500), 256, smem12>>>();
    scan_layer_kernel<<<BATCH, HDIM>>>(b1, tau_n1, tau_m1, 0);
    gemm2_k<<<dim3(4, 500), 256, smem12>>>();
    scan_layer_kernel<<<BATCH, HDIM>>>(b2, tau_n2, tau_m2, 1);
    gemm3_k<<<dim3(1, 500), 256, smem3>>>();
    scan_readout_kernel<<<BATCH, 32>>>(br, tau_mr, warm, out);
}